// round 15
// baseline (speedup 1.0000x reference)
#include <cuda_runtime.h>
#include <cuda_bf16.h>
#include <math.h>

#define NN      100000
#define F_IN    256
#define HID     64
#define H1      8
#define C1      8
#define NC      40
#define E_MAX   1700000
#define NEG_SLOPE 0.2f
#define AST     132

// ---------------- packed f32x2 helpers ----------------------------------------
__device__ __forceinline__ unsigned long long ffma2(
    unsigned long long a, unsigned long long b, unsigned long long c) {
    unsigned long long d;
    asm("fma.rn.f32x2 %0, %1, %2, %3;" : "=l"(d) : "l"(a), "l"(b), "l"(c));
    return d;
}
__device__ __forceinline__ unsigned long long pack2(float lo, float hi) {
    unsigned long long d;
    asm("mov.b64 %0, {%1, %2};" : "=l"(d) : "f"(lo), "f"(hi));
    return d;
}
__device__ __forceinline__ void unpack2(unsigned long long v, float& lo, float& hi) {
    asm("mov.b64 {%0, %1}, %2;" : "=f"(lo), "=f"(hi) : "l"(v));
}

// ---------------- scratch -----------------------------------------------------
__device__ int   g_is64;
__device__ int   g_deg[NN];
__device__ int   g_rowptr[NN + 1];
__device__ int   g_fill[NN];
__device__ int   g_col[E_MAX];
__device__ int   g_bsum[256];
__device__ float g_h1[(long)NN * HID];
__device__ float g_as1[NN * H1];
__device__ float g_ad1[NN * H1];
__device__ float g_h1o[(long)NN * HID];
__device__ float g_h2[(long)NN * NC];
__device__ float g_as2[NN];
__device__ float g_ad2[NN];

// -------- init: zero degrees + edge dtype detection (block 0) -----------------
__global__ void k_init(const void* ei, int EC) {
    int i = blockIdx.x * blockDim.x + threadIdx.x;
    if (i < NN) g_deg[i] = 0;
    if (blockIdx.x == 0) {
        __shared__ int bad;
        if (threadIdx.x == 0) bad = 0;
        __syncthreads();
        const long long* p = (const long long*)ei;
        int n = EC < 256 ? EC : 256;
        if ((int)threadIdx.x < n) {
            long long v = p[threadIdx.x];
            if (v < 0 || v >= NN) atomicExch(&bad, 1);
        }
        __syncthreads();
        if (threadIdx.x == 0) g_is64 = bad ? 0 : 1;
    }
}

__device__ __forceinline__ int edge_at(const void* ei, int idx) {
    return g_is64 ? (int)((const long long*)ei)[idx] : ((const int*)ei)[idx];
}

// ---------------- CSR build ---------------------------------------------------
__global__ void k_hist(const void* ei, int EC) {
    int i = blockIdx.x * blockDim.x + threadIdx.x;
    if (i < EC) {
        int d = edge_at(ei, EC + i);
        if (d >= 0 && d < NN) atomicAdd(&g_deg[d], 1);
    }
}

__global__ void k_scan_block() {
    __shared__ int ws[32];
    int tid = threadIdx.x;
    int gid = blockIdx.x * 1024 + tid;
    int v = (gid < NN) ? g_deg[gid] : 0;
    int x = v;
    #pragma unroll
    for (int o = 1; o < 32; o <<= 1) {
        int t = __shfl_up_sync(0xffffffffu, x, o);
        if ((tid & 31) >= o) x += t;
    }
    if ((tid & 31) == 31) ws[tid >> 5] = x;
    __syncthreads();
    if (tid < 32) {
        int w = ws[tid];
        int y = w;
        #pragma unroll
        for (int o = 1; o < 32; o <<= 1) {
            int t = __shfl_up_sync(0xffffffffu, y, o);
            if (tid >= o) y += t;
        }
        ws[tid] = y - w;
    }
    __syncthreads();
    int incl = x + ws[tid >> 5];
    if (gid < NN) g_rowptr[gid] = incl - v;
    if (tid == 1023) g_bsum[blockIdx.x] = incl;
}

__global__ void k_scan_tops(int nblocks) {
    int lane = threadIdx.x;
    int run = 0;
    for (int base = 0; base < nblocks; base += 32) {
        int idx = base + lane;
        int v = (idx < nblocks) ? g_bsum[idx] : 0;
        int x = v;
        #pragma unroll
        for (int o = 1; o < 32; o <<= 1) {
            int t = __shfl_up_sync(0xffffffffu, x, o);
            if (lane >= o) x += t;
        }
        if (idx < nblocks) g_bsum[idx] = run + x - v;
        run += __shfl_sync(0xffffffffu, x, 31);
    }
}

__global__ void k_scan_fix(int EC) {
    int gid = blockIdx.x * 1024 + threadIdx.x;
    if (gid < NN) {
        int v = g_rowptr[gid] + g_bsum[gid >> 10];
        g_rowptr[gid] = v;
        g_fill[gid] = v;
    }
    if (gid == 0) g_rowptr[NN] = EC;
}

__global__ void k_scatter(const void* ei, int EC) {
    int i = blockIdx.x * blockDim.x + threadIdx.x;
    if (i < EC) {
        int s = edge_at(ei, i);
        int d = edge_at(ei, EC + i);
        if (d >= 0 && d < NN) {
            int p = atomicAdd(&g_fill[d], 1);
            if (p >= 0 && p < E_MAX) g_col[p] = s;
        }
    }
}

// ------- GEMM1 (R7 form: 128x64 tile, FFMA2 inner) + fused alpha epilogue -----
__global__ void __launch_bounds__(256) k_gemm1(
    const float* __restrict__ X, const float* __restrict__ W,
    const float* __restrict__ att_s, const float* __restrict__ att_d) {
    __shared__ __align__(16) float sm[128 * 65];
    float* Ast = sm;
    float* Bs  = sm + 32 * AST;
    int tid = threadIdx.x;
    int r0 = blockIdx.x * 128;
    int tx = tid & 15, ty = tid >> 4;

    unsigned long long acc2[4][4];
    unsigned long long z = pack2(0.f, 0.f);
    #pragma unroll
    for (int p = 0; p < 4; p++)
        #pragma unroll
        for (int c = 0; c < 4; c++) acc2[p][c] = z;

    for (int k0 = 0; k0 < F_IN; k0 += 32) {
        #pragma unroll
        for (int l = 0; l < 4; l++) {
            int slot = tid + l * 256;
            int row = slot >> 3;
            int f4 = slot & 7;
            int gr = r0 + row;
            float4 v = make_float4(0.f, 0.f, 0.f, 0.f);
            if (gr < NN) v = *(const float4*)(X + (long)gr * F_IN + k0 + f4 * 4);
            Ast[(f4 * 4 + 0) * AST + row] = v.x;
            Ast[(f4 * 4 + 1) * AST + row] = v.y;
            Ast[(f4 * 4 + 2) * AST + row] = v.z;
            Ast[(f4 * 4 + 3) * AST + row] = v.w;
        }
        #pragma unroll
        for (int l = 0; l < 2; l++) {
            int slot = tid + l * 256;
            int kk = slot >> 4;
            int cv = slot & 15;
            *(float4*)&Bs[kk * 64 + cv * 4] = *(const float4*)(W + (k0 + kk) * HID + cv * 4);
        }
        __syncthreads();
        #pragma unroll
        for (int kk = 0; kk < 32; kk++) {
            float4 bv = *(const float4*)&Bs[kk * 64 + tx * 4];
            unsigned long long br[4];
            br[0] = pack2(bv.x, bv.x);
            br[1] = pack2(bv.y, bv.y);
            br[2] = pack2(bv.z, bv.z);
            br[3] = pack2(bv.w, bv.w);
            const float* ab = Ast + kk * AST + ty * 8;
            #pragma unroll
            for (int p = 0; p < 4; p++) {
                unsigned long long ap = *(const unsigned long long*)(ab + 2 * p);
                acc2[p][0] = ffma2(ap, br[0], acc2[p][0]);
                acc2[p][1] = ffma2(ap, br[1], acc2[p][1]);
                acc2[p][2] = ffma2(ap, br[2], acc2[p][2]);
                acc2[p][3] = ffma2(ap, br[3], acc2[p][3]);
            }
        }
        __syncthreads();
    }

    float* hbuf = sm;
    #pragma unroll
    for (int p = 0; p < 4; p++) {
        float lo[4], hi[4];
        #pragma unroll
        for (int c = 0; c < 4; c++) unpack2(acc2[p][c], lo[c], hi[c]);
        int lr = ty * 8 + 2 * p;
        int gr = r0 + lr;
        #pragma unroll
        for (int c = 0; c < 4; c++) {
            hbuf[lr * 65 + tx * 4 + c] = lo[c];
            hbuf[(lr + 1) * 65 + tx * 4 + c] = hi[c];
        }
        if (gr < NN) {
            #pragma unroll
            for (int c = 0; c < 4; c++)
                g_h1[(long)gr * HID + tx * 4 + c] = lo[c];
        }
        if (gr + 1 < NN) {
            #pragma unroll
            for (int c = 0; c < 4; c++)
                g_h1[(long)(gr + 1) * HID + tx * 4 + c] = hi[c];
        }
    }
    __syncthreads();

    #pragma unroll
    for (int t = 0; t < 4; t++) {
        int item = tid + t * 256;
        int lr = item >> 3, h = item & 7;
        int gr = r0 + lr;
        if (gr < NN) {
            const float* hp = hbuf + lr * 65 + h * C1;
            float as = 0.f, ad = 0.f;
            #pragma unroll
            for (int c = 0; c < C1; c++) {
                float hv = hp[c];
                as += hv * __ldg(att_s + h * C1 + c);
                ad += hv * __ldg(att_d + h * C1 + c);
            }
            g_as1[gr * H1 + h] = as;
            g_ad1[gr * H1 + h] = ad;
        }
    }
}

// -------- layer 1 aggregation: TWO warps per dst, R7 loop per half + elu ------
// Even warp takes edges [start, start+ceil(n/2)), odd warp the rest. Per-lane
// access pattern identical to R7; halves combine via smem (lo,hi,den per lane).
__global__ void __launch_bounds__(256) k_agg1(const float* __restrict__ b1) {
    __shared__ float sP[4][32][3];
    int tid = threadIdx.x;
    int wslot = tid >> 5;
    int lane = tid & 31;
    int pair = wslot >> 1;
    int sub = wslot & 1;
    int d = blockIdx.x * 4 + pair;
    bool valid = d < NN;

    int h = lane >> 2;
    float ad = 0.f;
    int s0i = 0, e0i = 0;
    if (valid) {
        int start = g_rowptr[d], end = g_rowptr[d + 1];
        int n = end - start;
        int halfc = (n + 1) >> 1;          // even warp gets ceil
        s0i = start + sub * halfc;
        e0i = sub ? end : (start + halfc);
        ad = __ldg(g_ad1 + d * H1 + h);
    }

    unsigned long long acc = pack2(0.f, 0.f);
    float den = 0.f;
    int nl = e0i - s0i;
    int n2 = nl & ~1;
    const int* cp = g_col + s0i;

    #pragma unroll 2
    for (int i = 0; i < n2; i += 2) {
        int s0 = __ldg(cp + i);
        int s1 = __ldg(cp + i + 1);
        float e0 = __ldg(g_as1 + s0 * H1 + h) + ad;
        float e1 = __ldg(g_as1 + s1 * H1 + h) + ad;
        e0 = (e0 > 0.f) ? e0 : NEG_SLOPE * e0;
        e1 = (e1 > 0.f) ? e1 : NEG_SLOPE * e1;
        float w0 = __expf(e0);
        float w1 = __expf(e1);
        unsigned long long hv0 = *(const unsigned long long*)(g_h1 + (long)s0 * HID + 2 * lane);
        unsigned long long hv1 = *(const unsigned long long*)(g_h1 + (long)s1 * HID + 2 * lane);
        den += w0 + w1;
        acc = ffma2(hv0, pack2(w0, w0), acc);
        acc = ffma2(hv1, pack2(w1, w1), acc);
    }
    if (n2 < nl) {
        int s0 = __ldg(cp + n2);
        float e0 = __ldg(g_as1 + s0 * H1 + h) + ad;
        e0 = (e0 > 0.f) ? e0 : NEG_SLOPE * e0;
        float w0 = __expf(e0);
        unsigned long long hv0 = *(const unsigned long long*)(g_h1 + (long)s0 * HID + 2 * lane);
        den += w0;
        acc = ffma2(hv0, pack2(w0, w0), acc);
    }
    float lo, hi;
    unpack2(acc, lo, hi);
    if (sub == 1) {
        sP[pair][lane][0] = lo;
        sP[pair][lane][1] = hi;
        sP[pair][lane][2] = den;
    }
    __syncthreads();
    if (sub == 0 && valid) {
        lo  += sP[pair][lane][0];
        hi  += sP[pair][lane][1];
        den += sP[pair][lane][2];
        float inv = 1.0f / den;
        float v0 = lo * inv + __ldg(b1 + 2 * lane);
        float v1 = hi * inv + __ldg(b1 + 2 * lane + 1);
        v0 = (v0 > 0.f) ? v0 : expm1f(v0);
        v1 = (v1 > 0.f) ? v1 : expm1f(v1);
        *(float2*)(g_h1o + (long)d * HID + 2 * lane) = make_float2(v0, v1);
    }
}

// ---------------- GEMM2 (R7 form: FFMA2 inner) + alpha2 -----------------------
__global__ void __launch_bounds__(128) k_gemm2(
    const float* __restrict__ W2,
    const float* __restrict__ att_s2, const float* __restrict__ att_d2) {
    __shared__ __align__(16) float Xs[128][65];
    __shared__ __align__(16) float Ws[HID][NC];
    __shared__ float Sa[NC], Sd[NC];
    int tid = threadIdx.x;
    int r0 = blockIdx.x * 128;
    for (int f = tid; f < HID * NC; f += 128) Ws[f / NC][f % NC] = W2[f];
    if (tid < NC) { Sa[tid] = att_s2[tid]; Sd[tid] = att_d2[tid]; }
    for (int f = tid; f < 128 * HID; f += 128) {
        int rr = f >> 6, cc = f & 63;
        int gr = r0 + rr;
        Xs[rr][cc] = (gr < NN) ? g_h1o[(long)gr * HID + cc] : 0.f;
    }
    __syncthreads();
    int r = r0 + tid;
    unsigned long long acc2[NC / 2];
    unsigned long long z = pack2(0.f, 0.f);
    #pragma unroll
    for (int c = 0; c < NC / 2; c++) acc2[c] = z;
    #pragma unroll 4
    for (int k = 0; k < HID; k++) {
        float xv = Xs[tid][k];
        unsigned long long xp = pack2(xv, xv);
        const unsigned long long* wp = (const unsigned long long*)&Ws[k][0];
        #pragma unroll
        for (int c = 0; c < NC / 2; c++) acc2[c] = ffma2(xp, wp[c], acc2[c]);
    }
    if (r < NN) {
        float a = 0.f, dd = 0.f;
        #pragma unroll
        for (int c = 0; c < NC / 2; c++) {
            float lo, hi;
            unpack2(acc2[c], lo, hi);
            g_h2[(long)r * NC + 2 * c]     = lo;
            g_h2[(long)r * NC + 2 * c + 1] = hi;
            a  += lo * Sa[2 * c] + hi * Sa[2 * c + 1];
            dd += lo * Sd[2 * c] + hi * Sd[2 * c + 1];
        }
        g_as2[r] = a;
        g_ad2[r] = dd;
    }
}

// ------ layer 2 aggregation: TWO warps per dst + log_softmax ------------------
__global__ void __launch_bounds__(256) k_agg2(const float* __restrict__ b2,
                                              float* __restrict__ out) {
    __shared__ float sP[4][32][3];
    int tid = threadIdx.x;
    int wslot = tid >> 5;
    int lane = tid & 31;
    int pair = wslot >> 1;
    int sub = wslot & 1;
    int d = blockIdx.x * 4 + pair;
    bool valid = d < NN;
    bool act = lane < 20;

    float ad = 0.f;
    int s0i = 0, e0i = 0;
    if (valid) {
        int start = g_rowptr[d], end = g_rowptr[d + 1];
        int n = end - start;
        int halfc = (n + 1) >> 1;
        s0i = start + sub * halfc;
        e0i = sub ? end : (start + halfc);
        ad = __ldg(g_ad2 + d);
    }

    unsigned long long acc = pack2(0.f, 0.f);
    float den = 0.f;
    int nl = e0i - s0i;
    int n2 = nl & ~1;
    const int* cp = g_col + s0i;

    #pragma unroll 2
    for (int i = 0; i < n2; i += 2) {
        int s0 = __ldg(cp + i);
        int s1 = __ldg(cp + i + 1);
        float e0 = __ldg(g_as2 + s0) + ad;
        float e1 = __ldg(g_as2 + s1) + ad;
        e0 = (e0 > 0.f) ? e0 : NEG_SLOPE * e0;
        e1 = (e1 > 0.f) ? e1 : NEG_SLOPE * e1;
        float w0 = __expf(e0);
        float w1 = __expf(e1);
        den += w0 + w1;
        if (act) {
            unsigned long long hv0 = *(const unsigned long long*)(g_h2 + (long)s0 * NC + 2 * lane);
            unsigned long long hv1 = *(const unsigned long long*)(g_h2 + (long)s1 * NC + 2 * lane);
            acc = ffma2(hv0, pack2(w0, w0), acc);
            acc = ffma2(hv1, pack2(w1, w1), acc);
        }
    }
    if (n2 < nl) {
        int s0 = __ldg(cp + n2);
        float e0 = __ldg(g_as2 + s0) + ad;
        e0 = (e0 > 0.f) ? e0 : NEG_SLOPE * e0;
        float w0 = __expf(e0);
        den += w0;
        if (act) {
            unsigned long long hv0 = *(const unsigned long long*)(g_h2 + (long)s0 * NC + 2 * lane);
            acc = ffma2(hv0, pack2(w0, w0), acc);
        }
    }
    float lo, hi;
    unpack2(acc, lo, hi);
    if (sub == 1) {
        sP[pair][lane][0] = lo;
        sP[pair][lane][1] = hi;
        sP[pair][lane][2] = den;
    }
    __syncthreads();
    if (sub == 0 && valid) {
        lo  += sP[pair][lane][0];
        hi  += sP[pair][lane][1];
        den += sP[pair][lane][2];
        float inv = 1.0f / den;
        float v0 = act ? (lo * inv + __ldg(b2 + 2 * lane))     : -3.0e38f;
        float v1 = act ? (hi * inv + __ldg(b2 + 2 * lane + 1)) : -3.0e38f;

        float m = fmaxf(v0, v1);
        #pragma unroll
        for (int o = 16; o >= 1; o >>= 1) m = fmaxf(m, __shfl_xor_sync(0xffffffffu, m, o));
        float se = act ? (__expf(v0 - m) + __expf(v1 - m)) : 0.f;
        #pragma unroll
        for (int o = 16; o >= 1; o >>= 1) se += __shfl_xor_sync(0xffffffffu, se, o);
        float lse = m + logf(se);

        if (act)
            *(float2*)(out + (long)d * NC + 2 * lane) = make_float2(v0 - lse, v1 - lse);
    }
}

// -----------------------------------------------------------------------------
extern "C" void kernel_launch(void* const* d_in, const int* in_sizes, int n_in,
                              void* d_out, int out_size) {
    const float* x        = (const float*)d_in[0];
    const float* W1       = (const float*)d_in[1];
    const float* att_src1 = (const float*)d_in[2];
    const float* att_dst1 = (const float*)d_in[3];
    const float* b1       = (const float*)d_in[4];
    const float* W2       = (const float*)d_in[5];
    const float* att_src2 = (const float*)d_in[6];
    const float* att_dst2 = (const float*)d_in[7];
    const float* b2       = (const float*)d_in[8];
    const void*  ei       = d_in[9];
    float* out = (float*)d_out;

    int EC = in_sizes[9] / 2;
    if (EC > E_MAX) EC = E_MAX;
    int nblocks = (NN + 1023) / 1024;

    cudaStream_t side;
    cudaStreamCreateWithFlags(&side, cudaStreamNonBlocking);
    cudaEvent_t evFork, evJoin;
    cudaEventCreateWithFlags(&evFork, cudaEventDisableTiming);
    cudaEventCreateWithFlags(&evJoin, cudaEventDisableTiming);

    cudaEventRecord(evFork, 0);
    cudaStreamWaitEvent(side, evFork, 0);
    k_gemm1<<<(NN + 127) / 128, 256, 0, side>>>(x, W1, att_src1, att_dst1);
    cudaEventRecord(evJoin, side);

    k_init<<<(NN + 255) / 256, 256>>>(ei, EC);
    k_hist<<<(EC + 255) / 256, 256>>>(ei, EC);
    k_scan_block<<<nblocks, 1024>>>();
    k_scan_tops<<<1, 32>>>(nblocks);
    k_scan_fix<<<nblocks, 1024>>>(EC);
    k_scatter<<<(EC + 255) / 256, 256>>>(ei, EC);

    cudaStreamWaitEvent(0, evJoin, 0);
    k_agg1<<<(NN + 3) / 4, 256>>>(b1);
    k_gemm2<<<(NN + 127) / 128, 128>>>(W2, att_src2, att_dst2);
    k_agg2<<<(NN + 3) / 4, 256>>>(b2, out);
}

// round 17
// speedup vs baseline: 1.0979x; 1.0979x over previous
#include <cuda_runtime.h>
#include <cuda_bf16.h>
#include <math.h>

#define NN      100000
#define F_IN    256
#define HID     64
#define H1      8
#define C1      8
#define NC      40
#define E_MAX   1700000
#define NEG_SLOPE 0.2f
#define AST     132

// ---------------- packed f32x2 helpers ----------------------------------------
__device__ __forceinline__ unsigned long long ffma2(
    unsigned long long a, unsigned long long b, unsigned long long c) {
    unsigned long long d;
    asm("fma.rn.f32x2 %0, %1, %2, %3;" : "=l"(d) : "l"(a), "l"(b), "l"(c));
    return d;
}
__device__ __forceinline__ unsigned long long pack2(float lo, float hi) {
    unsigned long long d;
    asm("mov.b64 %0, {%1, %2};" : "=l"(d) : "f"(lo), "f"(hi));
    return d;
}
__device__ __forceinline__ void unpack2(unsigned long long v, float& lo, float& hi) {
    asm("mov.b64 {%0, %1}, %2;" : "=f"(lo), "=f"(hi) : "l"(v));
}

// ---------------- scratch -----------------------------------------------------
__device__ int   g_is64;
__device__ int   g_deg[NN];
__device__ int   g_rowptr[NN + 1];
__device__ int   g_fill[NN];
__device__ int   g_col[E_MAX];
__device__ int   g_bsum[256];
__device__ float g_h1[(long)NN * HID];
__device__ float g_as1[NN * H1];
__device__ float g_ad1[NN * H1];
__device__ float g_h1o[(long)NN * HID];
__device__ float g_h2[(long)NN * NC];
__device__ float g_as2[NN];
__device__ float g_ad2[NN];

// -------- dtype detection (1 block; deg zeroed by memset node) ----------------
__global__ void k_detect(const void* ei, int EC) {
    __shared__ int bad;
    if (threadIdx.x == 0) bad = 0;
    __syncthreads();
    const long long* p = (const long long*)ei;
    int n = EC < 256 ? EC : 256;
    if ((int)threadIdx.x < n) {
        long long v = p[threadIdx.x];
        if (v < 0 || v >= NN) atomicExch(&bad, 1);
    }
    __syncthreads();
    if (threadIdx.x == 0) g_is64 = bad ? 0 : 1;
}

__device__ __forceinline__ int edge_at(const void* ei, int idx) {
    return g_is64 ? (int)((const long long*)ei)[idx] : ((const int*)ei)[idx];
}

// ---------------- CSR build: 4 edges/thread, loads front-batched --------------
// Thread t (t < q) handles edges {t, t+q, t+2q, t+3q}. Guard on t, NOT on i:
// excess threads (t >= q) must do nothing or chunk-boundary edges get counted
// twice (the round-16 correctness bug).
__global__ void k_hist(const void* ei, int EC) {
    int t = blockIdx.x * blockDim.x + threadIdx.x;
    int q = (EC + 3) >> 2;
    if (t >= q) return;
    int i0 = t, i1 = t + q, i2 = t + 2 * q, i3 = t + 3 * q;
    int d0 = edge_at(ei, EC + i0);
    int d1 = (i1 < EC) ? edge_at(ei, EC + i1) : -1;
    int d2 = (i2 < EC) ? edge_at(ei, EC + i2) : -1;
    int d3 = (i3 < EC) ? edge_at(ei, EC + i3) : -1;
    if (d0 >= 0 && d0 < NN) atomicAdd(&g_deg[d0], 1);
    if (d1 >= 0 && d1 < NN) atomicAdd(&g_deg[d1], 1);
    if (d2 >= 0 && d2 < NN) atomicAdd(&g_deg[d2], 1);
    if (d3 >= 0 && d3 < NN) atomicAdd(&g_deg[d3], 1);
}

__global__ void k_scan_block() {
    __shared__ int ws[32];
    int tid = threadIdx.x;
    int gid = blockIdx.x * 1024 + tid;
    int v = (gid < NN) ? g_deg[gid] : 0;
    int x = v;
    #pragma unroll
    for (int o = 1; o < 32; o <<= 1) {
        int t = __shfl_up_sync(0xffffffffu, x, o);
        if ((tid & 31) >= o) x += t;
    }
    if ((tid & 31) == 31) ws[tid >> 5] = x;
    __syncthreads();
    if (tid < 32) {
        int w = ws[tid];
        int y = w;
        #pragma unroll
        for (int o = 1; o < 32; o <<= 1) {
            int t = __shfl_up_sync(0xffffffffu, y, o);
            if (tid >= o) y += t;
        }
        ws[tid] = y - w;
    }
    __syncthreads();
    int incl = x + ws[tid >> 5];
    if (gid < NN) g_rowptr[gid] = incl - v;
    if (tid == 1023) g_bsum[blockIdx.x] = incl;
}

__global__ void k_scan_tops(int nblocks) {
    int lane = threadIdx.x;
    int run = 0;
    for (int base = 0; base < nblocks; base += 32) {
        int idx = base + lane;
        int v = (idx < nblocks) ? g_bsum[idx] : 0;
        int x = v;
        #pragma unroll
        for (int o = 1; o < 32; o <<= 1) {
            int t = __shfl_up_sync(0xffffffffu, x, o);
            if (lane >= o) x += t;
        }
        if (idx < nblocks) g_bsum[idx] = run + x - v;
        run += __shfl_sync(0xffffffffu, x, 31);
    }
}

__global__ void k_scan_fix(int EC) {
    int gid = blockIdx.x * 1024 + threadIdx.x;
    if (gid < NN) {
        int v = g_rowptr[gid] + g_bsum[gid >> 10];
        g_rowptr[gid] = v;
        g_fill[gid] = v;
    }
    if (gid == 0) g_rowptr[NN] = EC;
}

__global__ void k_scatter(const void* ei, int EC) {
    int t = blockIdx.x * blockDim.x + threadIdx.x;
    int q = (EC + 3) >> 2;
    if (t >= q) return;
    #pragma unroll
    for (int c = 0; c < 4; c++) {
        int i = t + c * q;
        if (i < EC) {
            int s = edge_at(ei, i);
            int d = edge_at(ei, EC + i);
            if (d >= 0 && d < NN) {
                int p = atomicAdd(&g_fill[d], 1);
                if (p >= 0 && p < E_MAX) g_col[p] = s;
            }
        }
    }
}

// ------- GEMM1 (R7 form: 128x64 tile, FFMA2 inner) + fused alpha epilogue -----
__global__ void __launch_bounds__(256) k_gemm1(
    const float* __restrict__ X, const float* __restrict__ W,
    const float* __restrict__ att_s, const float* __restrict__ att_d) {
    __shared__ __align__(16) float sm[128 * 65];
    float* Ast = sm;
    float* Bs  = sm + 32 * AST;
    int tid = threadIdx.x;
    int r0 = blockIdx.x * 128;
    int tx = tid & 15, ty = tid >> 4;

    unsigned long long acc2[4][4];
    unsigned long long z = pack2(0.f, 0.f);
    #pragma unroll
    for (int p = 0; p < 4; p++)
        #pragma unroll
        for (int c = 0; c < 4; c++) acc2[p][c] = z;

    for (int k0 = 0; k0 < F_IN; k0 += 32) {
        #pragma unroll
        for (int l = 0; l < 4; l++) {
            int slot = tid + l * 256;
            int row = slot >> 3;
            int f4 = slot & 7;
            int gr = r0 + row;
            float4 v = make_float4(0.f, 0.f, 0.f, 0.f);
            if (gr < NN) v = *(const float4*)(X + (long)gr * F_IN + k0 + f4 * 4);
            Ast[(f4 * 4 + 0) * AST + row] = v.x;
            Ast[(f4 * 4 + 1) * AST + row] = v.y;
            Ast[(f4 * 4 + 2) * AST + row] = v.z;
            Ast[(f4 * 4 + 3) * AST + row] = v.w;
        }
        #pragma unroll
        for (int l = 0; l < 2; l++) {
            int slot = tid + l * 256;
            int kk = slot >> 4;
            int cv = slot & 15;
            *(float4*)&Bs[kk * 64 + cv * 4] = *(const float4*)(W + (k0 + kk) * HID + cv * 4);
        }
        __syncthreads();
        #pragma unroll
        for (int kk = 0; kk < 32; kk++) {
            float4 bv = *(const float4*)&Bs[kk * 64 + tx * 4];
            unsigned long long br[4];
            br[0] = pack2(bv.x, bv.x);
            br[1] = pack2(bv.y, bv.y);
            br[2] = pack2(bv.z, bv.z);
            br[3] = pack2(bv.w, bv.w);
            const float* ab = Ast + kk * AST + ty * 8;
            #pragma unroll
            for (int p = 0; p < 4; p++) {
                unsigned long long ap = *(const unsigned long long*)(ab + 2 * p);
                acc2[p][0] = ffma2(ap, br[0], acc2[p][0]);
                acc2[p][1] = ffma2(ap, br[1], acc2[p][1]);
                acc2[p][2] = ffma2(ap, br[2], acc2[p][2]);
                acc2[p][3] = ffma2(ap, br[3], acc2[p][3]);
            }
        }
        __syncthreads();
    }

    float* hbuf = sm;
    #pragma unroll
    for (int p = 0; p < 4; p++) {
        float lo[4], hi[4];
        #pragma unroll
        for (int c = 0; c < 4; c++) unpack2(acc2[p][c], lo[c], hi[c]);
        int lr = ty * 8 + 2 * p;
        int gr = r0 + lr;
        #pragma unroll
        for (int c = 0; c < 4; c++) {
            hbuf[lr * 65 + tx * 4 + c] = lo[c];
            hbuf[(lr + 1) * 65 + tx * 4 + c] = hi[c];
        }
        if (gr < NN) {
            #pragma unroll
            for (int c = 0; c < 4; c++)
                g_h1[(long)gr * HID + tx * 4 + c] = lo[c];
        }
        if (gr + 1 < NN) {
            #pragma unroll
            for (int c = 0; c < 4; c++)
                g_h1[(long)(gr + 1) * HID + tx * 4 + c] = hi[c];
        }
    }
    __syncthreads();

    #pragma unroll
    for (int t = 0; t < 4; t++) {
        int item = tid + t * 256;
        int lr = item >> 3, h = item & 7;
        int gr = r0 + lr;
        if (gr < NN) {
            const float* hp = hbuf + lr * 65 + h * C1;
            float as = 0.f, ad = 0.f;
            #pragma unroll
            for (int c = 0; c < C1; c++) {
                float hv = hp[c];
                as += hv * __ldg(att_s + h * C1 + c);
                ad += hv * __ldg(att_d + h * C1 + c);
            }
            g_as1[gr * H1 + h] = as;
            g_ad1[gr * H1 + h] = ad;
        }
    }
}

// -------- layer 1 aggregation (R7 final form): shfl-free, 2-edge ILP + elu ----
__global__ void k_agg1(const float* __restrict__ b1) {
    int warp = (blockIdx.x * blockDim.x + threadIdx.x) >> 5;
    int lane = threadIdx.x & 31;
    if (warp >= NN) return;
    int d = warp;
    int start = g_rowptr[d], end = g_rowptr[d + 1];
    int h = lane >> 2;
    float ad = __ldg(g_ad1 + d * H1 + h);

    unsigned long long acc = pack2(0.f, 0.f);
    float den = 0.f;
    int n = end - start;
    int n2 = n & ~1;
    const int* cp = g_col + start;

    #pragma unroll 2
    for (int i = 0; i < n2; i += 2) {
        int s0 = __ldg(cp + i);
        int s1 = __ldg(cp + i + 1);
        float e0 = __ldg(g_as1 + s0 * H1 + h) + ad;
        float e1 = __ldg(g_as1 + s1 * H1 + h) + ad;
        e0 = (e0 > 0.f) ? e0 : NEG_SLOPE * e0;
        e1 = (e1 > 0.f) ? e1 : NEG_SLOPE * e1;
        float w0 = __expf(e0);
        float w1 = __expf(e1);
        unsigned long long hv0 = *(const unsigned long long*)(g_h1 + (long)s0 * HID + 2 * lane);
        unsigned long long hv1 = *(const unsigned long long*)(g_h1 + (long)s1 * HID + 2 * lane);
        den += w0 + w1;
        acc = ffma2(hv0, pack2(w0, w0), acc);
        acc = ffma2(hv1, pack2(w1, w1), acc);
    }
    if (n2 < n) {
        int s0 = __ldg(cp + n2);
        float e0 = __ldg(g_as1 + s0 * H1 + h) + ad;
        e0 = (e0 > 0.f) ? e0 : NEG_SLOPE * e0;
        float w0 = __expf(e0);
        unsigned long long hv0 = *(const unsigned long long*)(g_h1 + (long)s0 * HID + 2 * lane);
        den += w0;
        acc = ffma2(hv0, pack2(w0, w0), acc);
    }
    float inv = 1.0f / den;
    float lo, hi;
    unpack2(acc, lo, hi);
    float v0 = lo * inv + __ldg(b1 + 2 * lane);
    float v1 = hi * inv + __ldg(b1 + 2 * lane + 1);
    v0 = (v0 > 0.f) ? v0 : expm1f(v0);
    v1 = (v1 > 0.f) ? v1 : expm1f(v1);
    *(float2*)(g_h1o + (long)d * HID + 2 * lane) = make_float2(v0, v1);
}

// ---------------- GEMM2 (R7 form: FFMA2 inner) + alpha2 -----------------------
__global__ void __launch_bounds__(128) k_gemm2(
    const float* __restrict__ W2,
    const float* __restrict__ att_s2, const float* __restrict__ att_d2) {
    __shared__ __align__(16) float Xs[128][65];
    __shared__ __align__(16) float Ws[HID][NC];
    __shared__ float Sa[NC], Sd[NC];
    int tid = threadIdx.x;
    int r0 = blockIdx.x * 128;
    for (int f = tid; f < HID * NC; f += 128) Ws[f / NC][f % NC] = W2[f];
    if (tid < NC) { Sa[tid] = att_s2[tid]; Sd[tid] = att_d2[tid]; }
    for (int f = tid; f < 128 * HID; f += 128) {
        int rr = f >> 6, cc = f & 63;
        int gr = r0 + rr;
        Xs[rr][cc] = (gr < NN) ? g_h1o[(long)gr * HID + cc] : 0.f;
    }
    __syncthreads();
    int r = r0 + tid;
    unsigned long long acc2[NC / 2];
    unsigned long long z = pack2(0.f, 0.f);
    #pragma unroll
    for (int c = 0; c < NC / 2; c++) acc2[c] = z;
    #pragma unroll 4
    for (int k = 0; k < HID; k++) {
        float xv = Xs[tid][k];
        unsigned long long xp = pack2(xv, xv);
        const unsigned long long* wp = (const unsigned long long*)&Ws[k][0];
        #pragma unroll
        for (int c = 0; c < NC / 2; c++) acc2[c] = ffma2(xp, wp[c], acc2[c]);
    }
    if (r < NN) {
        float a = 0.f, dd = 0.f;
        #pragma unroll
        for (int c = 0; c < NC / 2; c++) {
            float lo, hi;
            unpack2(acc2[c], lo, hi);
            g_h2[(long)r * NC + 2 * c]     = lo;
            g_h2[(long)r * NC + 2 * c + 1] = hi;
            a  += lo * Sa[2 * c] + hi * Sa[2 * c + 1];
            dd += lo * Sd[2 * c] + hi * Sd[2 * c + 1];
        }
        g_as2[r] = a;
        g_ad2[r] = dd;
    }
}

// --------- layer 2 aggregation (R7 final form) + log_softmax ------------------
__global__ void k_agg2(const float* __restrict__ b2, float* __restrict__ out) {
    int warp = (blockIdx.x * blockDim.x + threadIdx.x) >> 5;
    int lane = threadIdx.x & 31;
    if (warp >= NN) return;
    int d = warp;
    int start = g_rowptr[d], end = g_rowptr[d + 1];
    float ad = __ldg(g_ad2 + d);
    bool act = lane < 20;

    unsigned long long acc = pack2(0.f, 0.f);
    float den = 0.f;
    int n = end - start;
    int n2 = n & ~1;
    const int* cp = g_col + start;

    #pragma unroll 2
    for (int i = 0; i < n2; i += 2) {
        int s0 = __ldg(cp + i);
        int s1 = __ldg(cp + i + 1);
        float e0 = __ldg(g_as2 + s0) + ad;
        float e1 = __ldg(g_as2 + s1) + ad;
        e0 = (e0 > 0.f) ? e0 : NEG_SLOPE * e0;
        e1 = (e1 > 0.f) ? e1 : NEG_SLOPE * e1;
        float w0 = __expf(e0);
        float w1 = __expf(e1);
        den += w0 + w1;
        if (act) {
            unsigned long long hv0 = *(const unsigned long long*)(g_h2 + (long)s0 * NC + 2 * lane);
            unsigned long long hv1 = *(const unsigned long long*)(g_h2 + (long)s1 * NC + 2 * lane);
            acc = ffma2(hv0, pack2(w0, w0), acc);
            acc = ffma2(hv1, pack2(w1, w1), acc);
        }
    }
    if (n2 < n) {
        int s0 = __ldg(cp + n2);
        float e0 = __ldg(g_as2 + s0) + ad;
        e0 = (e0 > 0.f) ? e0 : NEG_SLOPE * e0;
        float w0 = __expf(e0);
        den += w0;
        if (act) {
            unsigned long long hv0 = *(const unsigned long long*)(g_h2 + (long)s0 * NC + 2 * lane);
            acc = ffma2(hv0, pack2(w0, w0), acc);
        }
    }
    float inv = 1.0f / den;
    float lo, hi;
    unpack2(acc, lo, hi);
    float v0 = act ? (lo * inv + __ldg(b2 + 2 * lane))     : -3.0e38f;
    float v1 = act ? (hi * inv + __ldg(b2 + 2 * lane + 1)) : -3.0e38f;

    float m = fmaxf(v0, v1);
    #pragma unroll
    for (int o = 16; o >= 1; o >>= 1) m = fmaxf(m, __shfl_xor_sync(0xffffffffu, m, o));
    float se = act ? (__expf(v0 - m) + __expf(v1 - m)) : 0.f;
    #pragma unroll
    for (int o = 16; o >= 1; o >>= 1) se += __shfl_xor_sync(0xffffffffu, se, o);
    float lse = m + logf(se);

    if (act)
        *(float2*)(out + (long)d * NC + 2 * lane) = make_float2(v0 - lse, v1 - lse);
}

// -----------------------------------------------------------------------------
extern "C" void kernel_launch(void* const* d_in, const int* in_sizes, int n_in,
                              void* d_out, int out_size) {
    const float* x        = (const float*)d_in[0];
    const float* W1       = (const float*)d_in[1];
    const float* att_src1 = (const float*)d_in[2];
    const float* att_dst1 = (const float*)d_in[3];
    const float* b1       = (const float*)d_in[4];
    const float* W2       = (const float*)d_in[5];
    const float* att_src2 = (const float*)d_in[6];
    const float* att_dst2 = (const float*)d_in[7];
    const float* b2       = (const float*)d_in[8];
    const void*  ei       = d_in[9];
    float* out = (float*)d_out;

    int EC = in_sizes[9] / 2;
    if (EC > E_MAX) EC = E_MAX;
    int nblocks = (NN + 1023) / 1024;
    int q = (EC + 3) >> 2;                 // per-chunk element count for 4x ILP

    cudaStream_t side;
    cudaStreamCreateWithFlags(&side, cudaStreamNonBlocking);
    cudaEvent_t evFork, evJoin;
    cudaEventCreateWithFlags(&evFork, cudaEventDisableTiming);
    cudaEventCreateWithFlags(&evJoin, cudaEventDisableTiming);

    cudaEventRecord(evFork, 0);
    cudaStreamWaitEvent(side, evFork, 0);
    k_gemm1<<<(NN + 127) / 128, 256, 0, side>>>(x, W1, att_src1, att_dst1);
    cudaEventRecord(evJoin, side);

    void* degPtr = nullptr;
    cudaGetSymbolAddress(&degPtr, g_deg);
    cudaMemsetAsync(degPtr, 0, NN * sizeof(int), 0);
    k_detect<<<1, 256>>>(ei, EC);
    k_hist<<<(q + 255) / 256, 256>>>(ei, EC);
    k_scan_block<<<nblocks, 1024>>>();
    k_scan_tops<<<1, 32>>>(nblocks);
    k_scan_fix<<<nblocks, 1024>>>(EC);
    k_scatter<<<(q + 255) / 256, 256>>>(ei, EC);

    cudaStreamWaitEvent(0, evJoin, 0);
    k_agg1<<<(NN * 32 + 255) / 256, 256>>>(b1);
    k_gemm2<<<(NN + 127) / 128, 128>>>(W2, att_src2, att_dst2);
    k_agg2<<<(NN * 32 + 255) / 256, 256>>>(b2, out);
}